// round 15
// baseline (speedup 1.0000x reference)
#include <cuda_runtime.h>
#include <cuda_fp16.h>
#include <cstdint>

#define B_  64
#define I_  2048
#define D_  16
#define J_  32
#define E_  32
#define JE_ 1024

// u_hat: plain [b][i][j][e] fp16, half2 pairs over e. Row = 512 half2 = 2KB.
__device__ __align__(16) __half2 g_uhat[(size_t)B_ * I_ * 512];  // 268 MB
// per-round s accumulators (round r writes g_sbuf[r])
__device__ __align__(16) float g_sbuf[3][B_ * JE_];

// ---------------------------------------------------------------------------
// packed fp32x2 helpers (SASS FFMA2 — only reachable via PTX fma.rn.f32x2)
// ---------------------------------------------------------------------------
__device__ __forceinline__ unsigned long long pk2(float a, float b) {
    unsigned long long r;
    asm("mov.b64 %0, {%1, %2};" : "=l"(r) : "f"(a), "f"(b));
    return r;
}
__device__ __forceinline__ void fma2(unsigned long long& d,
                                     unsigned long long a, unsigned long long b) {
    asm("fma.rn.f32x2 %0, %1, %2, %0;" : "+l"(d) : "l"(a), "l"(b));
}
__device__ __forceinline__ float2 upk(unsigned long long v) {
    float2 r;
    asm("mov.b64 {%0, %1}, %2;" : "=f"(r.x), "=f"(r.y) : "l"(v));
    return r;
}

// cp.async helpers ("memory" clobbers order ring SMEM accesses vs commit/wait)
__device__ __forceinline__ void cp16(unsigned int smem_dst, const void* gsrc) {
    asm volatile("cp.async.cg.shared.global [%0], [%1], 16;"
                 :: "r"(smem_dst), "l"(gsrc) : "memory");
}
__device__ __forceinline__ void cp_commit() {
    asm volatile("cp.async.commit_group;" ::: "memory");
}
__device__ __forceinline__ void cp_wait3() {
    asm volatile("cp.async.wait_group 3;" ::: "memory");
}

// ---------------------------------------------------------------------------
// u_hat creation (R14 best): TWO CTAs per i (j split 16+16), e-paired
// accumulators -> epilogue is pure cvt+STG.32. First 256 CTAs zero g_sbuf.
// ---------------------------------------------------------------------------
__global__ void __launch_bounds__(256, 2) create_uhat_kernel(
    const float* __restrict__ x, const float* __restrict__ W) {
    extern __shared__ float smem[];
    float* sW = smem;           // 16*512 = 8192 floats (32 KB)
    float* sx = smem + 8192;    // 2048 floats (8 KB)

    const int bx = blockIdx.x;
    const int i = bx >> 1;
    const int h = bx & 1;
    const int t = threadIdx.x;
    const int l = t & 31;

    if (bx < 256) {                       // fused init of all 3 s-buffers
        g_sbuf[0][bx * 256 + t] = 0.f;
        g_sbuf[1][bx * 256 + t] = 0.f;
        g_sbuf[2][bx * 256 + t] = 0.f;
    }

    // ---- Stage W[h*16 .. h*16+15, i, :, :] into e-paired SMEM layout ----
    const float4* Wg = (const float4*)W;
    #pragma unroll
    for (int m = 0; m < 8; m++) {
        int k = t + 256 * m;
        int jl = k >> 7;                                  // local j 0..15
        int r = (k & 96) | ((l & 7) << 2) | (l >> 3);     // coalesced LDG lanes
        float4 v = Wg[(size_t)(h * 16 + jl) * (I_ * 128) + (size_t)i * 128 + r];
        int e = r >> 2, dc = r & 3;                       // d = dc*4 + c
        int colp = (((jl << 4) + (e >> 1)) ^ (dc << 2)) * 2 + (e & 1);
        float* base = sW + dc * 4 * 512 + colp;
        base[0]    = v.x;
        base[512]  = v.y;
        base[1024] = v.z;
        base[1536] = v.w;
    }
    // ---- Stage x[:, i, :] duplicated pairs: sx[(d*64 + b)*2] ----
    {
        int bb = t >> 2, dc = t & 3;
        float4 v = ((const float4*)x)[(size_t)(bb * I_ + i) * 4 + dc];
        *(float2*)&sx[((dc * 4 + 0) * 64 + bb) * 2] = make_float2(v.x, v.x);
        *(float2*)&sx[((dc * 4 + 1) * 64 + bb) * 2] = make_float2(v.y, v.y);
        *(float2*)&sx[((dc * 4 + 2) * 64 + bb) * 2] = make_float2(v.z, v.z);
        *(float2*)&sx[((dc * 4 + 3) * 64 + bb) * 2] = make_float2(v.w, v.w);
    }
    __syncthreads();

    const int tx = t & 31, ty = t >> 5;
    #pragma unroll 1
    for (int s = 0; s < 2; s++) {
        unsigned long long acc2[8][4];
        #pragma unroll
        for (int v = 0; v < 8; v++)
            #pragma unroll
            for (int u = 0; u < 4; u++) acc2[v][u] = 0ull;

        #pragma unroll 1
        for (int dc = 0; dc < 4; dc++) {
            #pragma unroll
            for (int c = 0; c < 4; c++) {
                const int d = dc * 4 + c;
                unsigned long long wp[4];
                #pragma unroll
                for (int u = 0; u < 4; u++) {
                    int cidx = s * 128 + u * 32 + tx;
                    wp[u] = *(const unsigned long long*)
                        (sW + d * 512 + ((cidx ^ (dc << 2)) * 2));
                }
                const float* xb = sx + d * 128 + ty * 2;
                #pragma unroll
                for (int v = 0; v < 8; v++) {
                    unsigned long long xd =
                        *(const unsigned long long*)(xb + v * 16);
                    #pragma unroll
                    for (int u = 0; u < 4; u++) fma2(acc2[v][u], xd, wp[u]);
                }
            }
        }

        #pragma unroll
        for (int v = 0; v < 8; v++) {
            __half2* base = g_uhat + ((size_t)(ty + 8 * v) * I_ + i) * 512
                          + h * 256;
            #pragma unroll
            for (int u = 0; u < 4; u++) {
                int cofs = s * 128 + u * 32 + tx;
                float2 f = upk(acc2[v][u]);
                base[cofs] = __floats2half2_rn(f.x, f.y);
            }
        }
    }
}

// ---------------------------------------------------------------------------
// Fused routing pass v6: lane = j, cp.async ring (4 slots, wait 3).
// Grid 512 (single wave): CTA = (b, chunk of 256 i); warp handles 64 rows.
// Squash is fused into the prologue: r>=1 computes oacc = squash(s0)
// (+ squash(s1) for r=2) in-lane from g_sbuf — no separate squash kernels,
// no g_oacc. Ring prefetch is issued BEFORE the prologue loads to overlap.
// ---------------------------------------------------------------------------
__global__ void __launch_bounds__(128, 4) routing_pass_kernel(int r, int rev) {
    __shared__ __align__(16) unsigned char ring[4][4][2048];  // 32 KB
    __shared__ float s_part[4 * 1024];                        // 16 KB

    const int t = threadIdx.x;
    const int w = t >> 5, l = t & 31;
    const int bb = blockIdx.x & 63;
    const int c0 = blockIdx.x >> 6;        // 0..7
    const int chunk = rev ? (7 - c0) : c0;
    const int rot = (l >> 1) & 3;          // per-lane chunk rotation

    // lane l's 64B segment of this warp's 64 rows (2048 B per row)
    const char* gb = (const char*)g_uhat
        + ((size_t)bb * I_ + chunk * 256 + w * 64) * 2048 + l * 64;
    const unsigned int rb =
        (unsigned int)__cvta_generic_to_shared(&ring[w][0][0]) + l * 64;

    // prologue: rows 0..2 into slots 0..2 (issued first to overlap with squash)
    #pragma unroll
    for (int q = 0; q < 3; q++) {
        #pragma unroll
        for (int k = 0; k < 4; k++)
            cp16(rb + q * 2048 + (((rot + k) & 3) * 16),
                 gb + (size_t)q * 2048 + k * 16);
        cp_commit();
    }

    // fused squash prologue: oacc = squash(s0) [+ squash(s1)]
    unsigned long long oa2[16];
    if (r > 0) {
        float4 v4[8];
        const float4* sp0 = (const float4*)(&g_sbuf[0][bb * JE_ + l * 32]);
        float sq = 0.f;
        #pragma unroll
        for (int k4 = 0; k4 < 8; k4++) {
            v4[k4] = sp0[k4];
            sq += v4[k4].x * v4[k4].x + v4[k4].y * v4[k4].y
                + v4[k4].z * v4[k4].z + v4[k4].w * v4[k4].w;
        }
        float sc = sq / ((1.f + sq) * sqrtf(sq + 1e-7f));
        #pragma unroll
        for (int k4 = 0; k4 < 8; k4++) {
            oa2[2 * k4]     = pk2(sc * v4[k4].x, sc * v4[k4].y);
            oa2[2 * k4 + 1] = pk2(sc * v4[k4].z, sc * v4[k4].w);
        }
        if (r == 2) {
            const float4* sp1 = (const float4*)(&g_sbuf[1][bb * JE_ + l * 32]);
            float sq1 = 0.f;
            #pragma unroll
            for (int k4 = 0; k4 < 8; k4++) {
                v4[k4] = sp1[k4];
                sq1 += v4[k4].x * v4[k4].x + v4[k4].y * v4[k4].y
                     + v4[k4].z * v4[k4].z + v4[k4].w * v4[k4].w;
            }
            float sc1 = sq1 / ((1.f + sq1) * sqrtf(sq1 + 1e-7f));
            unsigned long long scp = pk2(sc1, sc1);
            #pragma unroll
            for (int k4 = 0; k4 < 8; k4++) {
                fma2(oa2[2 * k4],     scp, pk2(v4[k4].x, v4[k4].y));
                fma2(oa2[2 * k4 + 1], scp, pk2(v4[k4].z, v4[k4].w));
            }
        }
    }

    unsigned long long acc2[16];
    #pragma unroll
    for (int k = 0; k < 16; k++) acc2[k] = 0ull;

    int slot = 0;
    #pragma unroll 1
    for (int row = 0; row < 64; row++) {
        if (row + 3 < 64) {
            int s2 = slot + 3;
            if (s2 >= 4) s2 -= 4;                 // (row+3) % 4
            #pragma unroll
            for (int k = 0; k < 4; k++)
                cp16(rb + s2 * 2048 + (((rot + k) & 3) * 16),
                     gb + (size_t)(row + 3) * 2048 + k * 16);
        }
        cp_commit();         // empty group on tail iterations keeps count law
        cp_wait3();          // row's group complete

        // consume lane's own 64B (e-chunks 0..3, de-rotated)
        const uint4* sp = (const uint4*)(&ring[w][slot][0]) + l * 4;
        uint4 q0 = sp[(rot + 0) & 3];
        uint4 q1 = sp[(rot + 1) & 3];
        uint4 q2 = sp[(rot + 2) & 3];
        uint4 q3 = sp[(rot + 3) & 3];
        slot = (slot == 3) ? 0 : slot + 1;

        unsigned long long u2[16];
        {
            const __half2* h0 = (const __half2*)&q0;
            const __half2* h1 = (const __half2*)&q1;
            const __half2* h2 = (const __half2*)&q2;
            const __half2* h3 = (const __half2*)&q3;
            #pragma unroll
            for (int k = 0; k < 4; k++) {
                float2 f;
                f = __half22float2(h0[k]); u2[k]      = pk2(f.x, f.y);
                f = __half22float2(h1[k]); u2[4 + k]  = pk2(f.x, f.y);
                f = __half22float2(h2[k]); u2[8 + k]  = pk2(f.x, f.y);
                f = __half22float2(h3[k]); u2[12 + k] = pk2(f.x, f.y);
            }
        }

        float c;
        if (r == 0) {
            c = 0.03125f;
        } else {
            unsigned long long lg2 = 0ull;
            #pragma unroll
            for (int k = 0; k < 16; k++) fma2(lg2, oa2[k], u2[k]);
            float2 lf = upk(lg2);
            float lg = lf.x + lf.y;
            float mx = lg;
            #pragma unroll
            for (int m = 16; m >= 1; m >>= 1)
                mx = fmaxf(mx, __shfl_xor_sync(0xffffffffu, mx, m));
            float ex = __expf(lg - mx);
            float sm = ex;
            #pragma unroll
            for (int m = 16; m >= 1; m >>= 1)
                sm += __shfl_xor_sync(0xffffffffu, sm, m);
            c = __fdividef(ex, sm);
        }
        unsigned long long c2 = pk2(c, c);
        #pragma unroll
        for (int k = 0; k < 16; k++) fma2(acc2[k], c2, u2[k]);
    }

    // Per-warp partials -> swizzled SMEM -> CTA reduce -> atomics into sbuf[r]
    #pragma unroll
    for (int k4 = 0; k4 < 8; k4++) {
        int phys = (k4 + l) & 7;
        float2 a = upk(acc2[2 * k4]), b = upk(acc2[2 * k4 + 1]);
        *(float4*)&s_part[w * 1024 + l * 32 + phys * 4] =
            make_float4(a.x, a.y, b.x, b.y);
    }
    __syncthreads();

    float* sout = g_sbuf[r];
    const int j = t >> 2;
    #pragma unroll
    for (int h = 0; h < 2; h++) {
        int k4 = (t & 3) * 2 + h;
        int phys = (k4 + j) & 7;
        float4 sum = *(const float4*)&s_part[j * 32 + phys * 4];
        #pragma unroll
        for (int w2 = 1; w2 < 4; w2++) {
            float4 v = *(const float4*)&s_part[w2 * 1024 + j * 32 + phys * 4];
            sum.x += v.x; sum.y += v.y; sum.z += v.z; sum.w += v.w;
        }
        float* sg = sout + bb * JE_ + j * 32 + k4 * 4;
        atomicAdd(sg + 0, sum.x);
        atomicAdd(sg + 1, sum.y);
        atomicAdd(sg + 2, sum.z);
        atomicAdd(sg + 3, sum.w);
    }
}

// ---------------------------------------------------------------------------
// final squash: reads g_sbuf[2], writes d_out. warp = one (b,j), lanes = e.
// ---------------------------------------------------------------------------
__global__ void __launch_bounds__(256) squash_final_kernel(float* __restrict__ out) {
    const int wg = blockIdx.x * 8 + (threadIdx.x >> 5);  // 0..2047
    const int bb = wg >> 5, j = wg & 31, e = threadIdx.x & 31;
    const int idx = bb * JE_ + j * 32 + e;
    float s = g_sbuf[2][idx];
    float sq = s * s;
    #pragma unroll
    for (int m = 16; m >= 1; m >>= 1)
        sq += __shfl_xor_sync(0xffffffffu, sq, m);
    float scale = sq / ((1.f + sq) * sqrtf(sq + 1e-7f));
    out[idx] = scale * s;
}

// ---------------------------------------------------------------------------
extern "C" void kernel_launch(void* const* d_in, const int* in_sizes, int n_in,
                              void* d_out, int out_size) {
    const float* x = (const float*)d_in[0];
    const float* W = (const float*)d_in[1];
    if (in_sizes[0] != B_ * I_ * D_) {
        x = (const float*)d_in[1];
        W = (const float*)d_in[0];
    }

    const int smem_bytes = (8192 + 2048) * sizeof(float);  // 40960 B
    cudaFuncSetAttribute(create_uhat_kernel,
                         cudaFuncAttributeMaxDynamicSharedMemorySize, smem_bytes);

    create_uhat_kernel<<<4096, 256, smem_bytes>>>(x, W);
    for (int r = 0; r < 3; r++)
        routing_pass_kernel<<<512, 128>>>(r, (r & 1) ? 0 : 1);
    squash_final_kernel<<<256, 256>>>((float*)d_out);
}

// round 16
// speedup vs baseline: 1.0489x; 1.0489x over previous
#include <cuda_runtime.h>
#include <cuda_fp16.h>
#include <cstdint>

#define B_  64
#define I_  2048
#define D_  16
#define J_  32
#define E_  32
#define JE_ 1024

// u_hat: plain [b][i][j][e] fp16, half2 pairs over e. Row = 512 half2 = 2KB.
__device__ __align__(16) __half2 g_uhat[(size_t)B_ * I_ * 512];  // 268 MB
// per-round s accumulators (round r writes g_sbuf[r])
__device__ __align__(16) float g_sbuf[3][B_ * JE_];

// ---------------------------------------------------------------------------
// packed fp32x2 helpers (SASS FFMA2 — only reachable via PTX fma.rn.f32x2)
// ---------------------------------------------------------------------------
__device__ __forceinline__ unsigned long long pk2(float a, float b) {
    unsigned long long r;
    asm("mov.b64 %0, {%1, %2};" : "=l"(r) : "f"(a), "f"(b));
    return r;
}
__device__ __forceinline__ void fma2(unsigned long long& d,
                                     unsigned long long a, unsigned long long b) {
    asm("fma.rn.f32x2 %0, %1, %2, %0;" : "+l"(d) : "l"(a), "l"(b));
}
__device__ __forceinline__ float2 upk(unsigned long long v) {
    float2 r;
    asm("mov.b64 {%0, %1}, %2;" : "=f"(r.x), "=f"(r.y) : "l"(v));
    return r;
}

// cp.async helpers ("memory" clobbers order ring SMEM accesses vs commit/wait)
__device__ __forceinline__ void cp16(unsigned int smem_dst, const void* gsrc) {
    asm volatile("cp.async.cg.shared.global [%0], [%1], 16;"
                 :: "r"(smem_dst), "l"(gsrc) : "memory");
}
__device__ __forceinline__ void cp_commit() {
    asm volatile("cp.async.commit_group;" ::: "memory");
}
__device__ __forceinline__ void cp_wait3() {
    asm volatile("cp.async.wait_group 3;" ::: "memory");
}

// ---------------------------------------------------------------------------
// u_hat creation (R14 best): TWO CTAs per i (j split 16+16), e-paired
// accumulators -> epilogue is pure cvt+STG.32. First 256 CTAs zero g_sbuf.
// ---------------------------------------------------------------------------
__global__ void __launch_bounds__(256, 2) create_uhat_kernel(
    const float* __restrict__ x, const float* __restrict__ W) {
    extern __shared__ float smem[];
    float* sW = smem;           // 16*512 = 8192 floats (32 KB)
    float* sx = smem + 8192;    // 2048 floats (8 KB)

    const int bx = blockIdx.x;
    const int i = bx >> 1;
    const int h = bx & 1;
    const int t = threadIdx.x;
    const int l = t & 31;

    if (bx < 256) {                       // fused init of all 3 s-buffers
        g_sbuf[0][bx * 256 + t] = 0.f;
        g_sbuf[1][bx * 256 + t] = 0.f;
        g_sbuf[2][bx * 256 + t] = 0.f;
    }

    // ---- Stage W[h*16 .. h*16+15, i, :, :] into e-paired SMEM layout ----
    const float4* Wg = (const float4*)W;
    #pragma unroll
    for (int m = 0; m < 8; m++) {
        int k = t + 256 * m;
        int jl = k >> 7;                                  // local j 0..15
        int r = (k & 96) | ((l & 7) << 2) | (l >> 3);     // coalesced LDG lanes
        float4 v = Wg[(size_t)(h * 16 + jl) * (I_ * 128) + (size_t)i * 128 + r];
        int e = r >> 2, dc = r & 3;                       // d = dc*4 + c
        int colp = (((jl << 4) + (e >> 1)) ^ (dc << 2)) * 2 + (e & 1);
        float* base = sW + dc * 4 * 512 + colp;
        base[0]    = v.x;
        base[512]  = v.y;
        base[1024] = v.z;
        base[1536] = v.w;
    }
    // ---- Stage x[:, i, :] duplicated pairs: sx[(d*64 + b)*2] ----
    {
        int bb = t >> 2, dc = t & 3;
        float4 v = ((const float4*)x)[(size_t)(bb * I_ + i) * 4 + dc];
        *(float2*)&sx[((dc * 4 + 0) * 64 + bb) * 2] = make_float2(v.x, v.x);
        *(float2*)&sx[((dc * 4 + 1) * 64 + bb) * 2] = make_float2(v.y, v.y);
        *(float2*)&sx[((dc * 4 + 2) * 64 + bb) * 2] = make_float2(v.z, v.z);
        *(float2*)&sx[((dc * 4 + 3) * 64 + bb) * 2] = make_float2(v.w, v.w);
    }
    __syncthreads();

    const int tx = t & 31, ty = t >> 5;
    #pragma unroll 1
    for (int s = 0; s < 2; s++) {
        unsigned long long acc2[8][4];
        #pragma unroll
        for (int v = 0; v < 8; v++)
            #pragma unroll
            for (int u = 0; u < 4; u++) acc2[v][u] = 0ull;

        #pragma unroll 1
        for (int dc = 0; dc < 4; dc++) {
            #pragma unroll
            for (int c = 0; c < 4; c++) {
                const int d = dc * 4 + c;
                unsigned long long wp[4];
                #pragma unroll
                for (int u = 0; u < 4; u++) {
                    int cidx = s * 128 + u * 32 + tx;
                    wp[u] = *(const unsigned long long*)
                        (sW + d * 512 + ((cidx ^ (dc << 2)) * 2));
                }
                const float* xb = sx + d * 128 + ty * 2;
                #pragma unroll
                for (int v = 0; v < 8; v++) {
                    unsigned long long xd =
                        *(const unsigned long long*)(xb + v * 16);
                    #pragma unroll
                    for (int u = 0; u < 4; u++) fma2(acc2[v][u], xd, wp[u]);
                }
            }
        }

        #pragma unroll
        for (int v = 0; v < 8; v++) {
            __half2* base = g_uhat + ((size_t)(ty + 8 * v) * I_ + i) * 512
                          + h * 256;
            #pragma unroll
            for (int u = 0; u < 4; u++) {
                int cofs = s * 128 + u * 32 + tx;
                float2 f = upk(acc2[v][u]);
                base[cofs] = __floats2half2_rn(f.x, f.y);
            }
        }
    }
}

// ---------------------------------------------------------------------------
// Fused routing pass v7 = R14 geometry (grid 1024, 32 rows/warp, ring-4)
// + R15's fused-squash prologue and per-round s-buffers.
// Squash(s) is in-lane (lane = j): oacc = squash(sbuf0) [+ squash(sbuf1)].
// Ring prefetch issued first so the prologue overlaps the initial DRAM lat.
// ---------------------------------------------------------------------------
__global__ void __launch_bounds__(128, 4) routing_pass_kernel(int r, int rev) {
    __shared__ __align__(16) unsigned char ring[4][4][2048];  // 32 KB
    __shared__ float s_part[4 * 1024];                        // 16 KB

    const int t = threadIdx.x;
    const int w = t >> 5, l = t & 31;
    const int bb = blockIdx.x & 63;
    const int c0 = blockIdx.x >> 6;        // 0..15, i-major across the grid
    const int chunk = rev ? (15 - c0) : c0;
    const int rot = (l >> 1) & 3;          // per-lane chunk rotation

    // lane l's 64B segment of this warp's 32 rows (2048 B per row)
    const char* gb = (const char*)g_uhat
        + ((size_t)bb * I_ + chunk * 128 + w * 32) * 2048 + l * 64;
    const unsigned int rb =
        (unsigned int)__cvta_generic_to_shared(&ring[w][0][0]) + l * 64;

    // prologue: rows 0..2 into slots 0..2 (issued first to overlap squash)
    #pragma unroll
    for (int q = 0; q < 3; q++) {
        #pragma unroll
        for (int k = 0; k < 4; k++)
            cp16(rb + q * 2048 + (((rot + k) & 3) * 16),
                 gb + (size_t)q * 2048 + k * 16);
        cp_commit();
    }

    // fused squash prologue: oacc = squash(s0) [+ squash(s1)]
    unsigned long long oa2[16];
    if (r > 0) {
        float4 v4[8];
        const float4* sp0 = (const float4*)(&g_sbuf[0][bb * JE_ + l * 32]);
        float sq = 0.f;
        #pragma unroll
        for (int k4 = 0; k4 < 8; k4++) {
            v4[k4] = sp0[k4];
            sq += v4[k4].x * v4[k4].x + v4[k4].y * v4[k4].y
                + v4[k4].z * v4[k4].z + v4[k4].w * v4[k4].w;
        }
        float sc = sq / ((1.f + sq) * sqrtf(sq + 1e-7f));
        #pragma unroll
        for (int k4 = 0; k4 < 8; k4++) {
            oa2[2 * k4]     = pk2(sc * v4[k4].x, sc * v4[k4].y);
            oa2[2 * k4 + 1] = pk2(sc * v4[k4].z, sc * v4[k4].w);
        }
        if (r == 2) {
            const float4* sp1 = (const float4*)(&g_sbuf[1][bb * JE_ + l * 32]);
            float sq1 = 0.f;
            #pragma unroll
            for (int k4 = 0; k4 < 8; k4++) {
                v4[k4] = sp1[k4];
                sq1 += v4[k4].x * v4[k4].x + v4[k4].y * v4[k4].y
                     + v4[k4].z * v4[k4].z + v4[k4].w * v4[k4].w;
            }
            float sc1 = sq1 / ((1.f + sq1) * sqrtf(sq1 + 1e-7f));
            unsigned long long scp = pk2(sc1, sc1);
            #pragma unroll
            for (int k4 = 0; k4 < 8; k4++) {
                fma2(oa2[2 * k4],     scp, pk2(v4[k4].x, v4[k4].y));
                fma2(oa2[2 * k4 + 1], scp, pk2(v4[k4].z, v4[k4].w));
            }
        }
    }

    unsigned long long acc2[16];
    #pragma unroll
    for (int k = 0; k < 16; k++) acc2[k] = 0ull;

    int slot = 0;
    #pragma unroll 1
    for (int row = 0; row < 32; row++) {
        if (row + 3 < 32) {
            int s2 = slot + 3;
            if (s2 >= 4) s2 -= 4;                 // (row+3) % 4
            #pragma unroll
            for (int k = 0; k < 4; k++)
                cp16(rb + s2 * 2048 + (((rot + k) & 3) * 16),
                     gb + (size_t)(row + 3) * 2048 + k * 16);
        }
        cp_commit();         // empty group on tail iterations keeps count law
        cp_wait3();          // row's group complete

        // consume lane's own 64B (e-chunks 0..3, de-rotated)
        const uint4* sp = (const uint4*)(&ring[w][slot][0]) + l * 4;
        uint4 q0 = sp[(rot + 0) & 3];
        uint4 q1 = sp[(rot + 1) & 3];
        uint4 q2 = sp[(rot + 2) & 3];
        uint4 q3 = sp[(rot + 3) & 3];
        slot = (slot == 3) ? 0 : slot + 1;

        unsigned long long u2[16];
        {
            const __half2* h0 = (const __half2*)&q0;
            const __half2* h1 = (const __half2*)&q1;
            const __half2* h2 = (const __half2*)&q2;
            const __half2* h3 = (const __half2*)&q3;
            #pragma unroll
            for (int k = 0; k < 4; k++) {
                float2 f;
                f = __half22float2(h0[k]); u2[k]      = pk2(f.x, f.y);
                f = __half22float2(h1[k]); u2[4 + k]  = pk2(f.x, f.y);
                f = __half22float2(h2[k]); u2[8 + k]  = pk2(f.x, f.y);
                f = __half22float2(h3[k]); u2[12 + k] = pk2(f.x, f.y);
            }
        }

        float c;
        if (r == 0) {
            c = 0.03125f;
        } else {
            unsigned long long lg2 = 0ull;
            #pragma unroll
            for (int k = 0; k < 16; k++) fma2(lg2, oa2[k], u2[k]);
            float2 lf = upk(lg2);
            float lg = lf.x + lf.y;
            float mx = lg;
            #pragma unroll
            for (int m = 16; m >= 1; m >>= 1)
                mx = fmaxf(mx, __shfl_xor_sync(0xffffffffu, mx, m));
            float ex = __expf(lg - mx);
            float sm = ex;
            #pragma unroll
            for (int m = 16; m >= 1; m >>= 1)
                sm += __shfl_xor_sync(0xffffffffu, sm, m);
            c = __fdividef(ex, sm);
        }
        unsigned long long c2 = pk2(c, c);
        #pragma unroll
        for (int k = 0; k < 16; k++) fma2(acc2[k], c2, u2[k]);
    }

    // Per-warp partials -> swizzled SMEM -> CTA reduce -> atomics into sbuf[r]
    #pragma unroll
    for (int k4 = 0; k4 < 8; k4++) {
        int phys = (k4 + l) & 7;
        float2 a = upk(acc2[2 * k4]), b = upk(acc2[2 * k4 + 1]);
        *(float4*)&s_part[w * 1024 + l * 32 + phys * 4] =
            make_float4(a.x, a.y, b.x, b.y);
    }
    __syncthreads();

    float* sout = g_sbuf[r];
    const int j = t >> 2;
    #pragma unroll
    for (int h = 0; h < 2; h++) {
        int k4 = (t & 3) * 2 + h;
        int phys = (k4 + j) & 7;
        float4 sum = *(const float4*)&s_part[j * 32 + phys * 4];
        #pragma unroll
        for (int w2 = 1; w2 < 4; w2++) {
            float4 v = *(const float4*)&s_part[w2 * 1024 + j * 32 + phys * 4];
            sum.x += v.x; sum.y += v.y; sum.z += v.z; sum.w += v.w;
        }
        float* sg = sout + bb * JE_ + j * 32 + k4 * 4;
        atomicAdd(sg + 0, sum.x);
        atomicAdd(sg + 1, sum.y);
        atomicAdd(sg + 2, sum.z);
        atomicAdd(sg + 3, sum.w);
    }
}

// ---------------------------------------------------------------------------
// final squash: reads g_sbuf[2], writes d_out. warp = one (b,j), lanes = e.
// ---------------------------------------------------------------------------
__global__ void __launch_bounds__(256) squash_final_kernel(float* __restrict__ out) {
    const int wg = blockIdx.x * 8 + (threadIdx.x >> 5);  // 0..2047
    const int bb = wg >> 5, j = wg & 31, e = threadIdx.x & 31;
    const int idx = bb * JE_ + j * 32 + e;
    float s = g_sbuf[2][idx];
    float sq = s * s;
    #pragma unroll
    for (int m = 16; m >= 1; m >>= 1)
        sq += __shfl_xor_sync(0xffffffffu, sq, m);
    float scale = sq / ((1.f + sq) * sqrtf(sq + 1e-7f));
    out[idx] = scale * s;
}

// ---------------------------------------------------------------------------
extern "C" void kernel_launch(void* const* d_in, const int* in_sizes, int n_in,
                              void* d_out, int out_size) {
    const float* x = (const float*)d_in[0];
    const float* W = (const float*)d_in[1];
    if (in_sizes[0] != B_ * I_ * D_) {
        x = (const float*)d_in[1];
        W = (const float*)d_in[0];
    }

    const int smem_bytes = (8192 + 2048) * sizeof(float);  // 40960 B
    cudaFuncSetAttribute(create_uhat_kernel,
                         cudaFuncAttributeMaxDynamicSharedMemorySize, smem_bytes);

    create_uhat_kernel<<<4096, 256, smem_bytes>>>(x, W);
    for (int r = 0; r < 3; r++)
        routing_pass_kernel<<<1024, 128>>>(r, (r & 1) ? 0 : 1);
    squash_final_kernel<<<256, 256>>>((float*)d_out);
}